// round 16
// baseline (speedup 1.0000x reference)
#include <cuda_runtime.h>
#include <cuda_bf16.h>

// FM layer: out[b,:] = 0.5 * ((sum v*e)^2 - sum (v*e)^2), batch_ids sorted.
//
// Pinned best configuration (empirical argmax over 15 rounds) + one isolated
// tweak: all single-use STREAM accesses (fids/vals/bids loads, output store)
// are evict-first (.cs), reserving L2 capacity for embedding-row reuse.
// The gather body is otherwise byte-identical to the 41.28us kernel.
//
//   * boundary_kernel: sorted batch_ids -> CSR row starts, 1 elem/thread,
//     exactly-once transition writes, no atomics.
//   * fm_main: 1 CTA per batch row, 8 groups x 32 threads (float2 lanes),
//     4-deep independent gather pipeline, 32 regs, 8 CTAs/SM (occ ~88%).
//     Pinned at the random-256B-row HBM ceiling (~4.3TB/s) across 7 variants.
//
// Inputs:
//   d_in[0] feature_embedding float32 [1e6, 64]
//   d_in[1] feature_vals      float32 [819200]
//   d_in[2] batch_ids         int32   [819200] sorted
//   d_in[3] feat_ids          int32   [819200]
//   d_in[4] batch_size        int32   [1]
// Output float32 [4096, 64]

#define EMBED  64
#define GROUPS 8              // 8 warps per CTA, group-strided over the segment
#define BLOCK  256

__device__ int g_starts[4097];

// Sorted batch_ids -> CSR row starts. Exactly-once, no atomics.
// bids is single-use -> evict-first loads.
__global__ void boundary_kernel(const int* __restrict__ bids, int nnz, int batch)
{
    int i = blockIdx.x * blockDim.x + threadIdx.x;
    if (i > nnz) return;
    int prev = (i == 0)   ? -1    : __ldcs(bids + i - 1);
    int cur  = (i == nnz) ? batch : __ldcs(bids + i);
    for (int b = prev + 1; b <= cur; b++)
        g_starts[b] = i;
}

__global__ __launch_bounds__(BLOCK, 8)
void fm_main(const float* __restrict__ emb,
             const float* __restrict__ vals,
             const int*   __restrict__ fids,
             float*       __restrict__ out)
{
    const int b = blockIdx.x;
    const int t = threadIdx.x & 31;     // float2 lane: dims [2t, 2t+1]
    const int g = threadIdx.x >> 5;     // warp/group 0..7

    const int lo = g_starts[b];
    const int hi = g_starts[b + 1];

    const float2* __restrict__ emb2 = (const float2*)emb;

    float sx = 0.f, sy = 0.f, qx = 0.f, qy = 0.f;

    int i = lo + g;
    // 4-deep independent gather pipeline per thread.
    // Streams (.cs, single-use) vs embedding gathers (__ldg, L2-cached).
    for (; i + 3 * GROUPS < hi; i += 4 * GROUPS) {
        int f0 = __ldcs(fids + i);
        int f1 = __ldcs(fids + i +     GROUPS);
        int f2 = __ldcs(fids + i + 2 * GROUPS);
        int f3 = __ldcs(fids + i + 3 * GROUPS);
        float v0 = __ldcs(vals + i);
        float v1 = __ldcs(vals + i +     GROUPS);
        float v2 = __ldcs(vals + i + 2 * GROUPS);
        float v3 = __ldcs(vals + i + 3 * GROUPS);
        float2 e0 = __ldg(emb2 + f0 * 32 + t);
        float2 e1 = __ldg(emb2 + f1 * 32 + t);
        float2 e2 = __ldg(emb2 + f2 * 32 + t);
        float2 e3 = __ldg(emb2 + f3 * 32 + t);

        float ax, ay;
        ax = v0 * e0.x; ay = v0 * e0.y; sx += ax; qx = fmaf(ax, ax, qx); sy += ay; qy = fmaf(ay, ay, qy);
        ax = v1 * e1.x; ay = v1 * e1.y; sx += ax; qx = fmaf(ax, ax, qx); sy += ay; qy = fmaf(ay, ay, qy);
        ax = v2 * e2.x; ay = v2 * e2.y; sx += ax; qx = fmaf(ax, ax, qx); sy += ay; qy = fmaf(ay, ay, qy);
        ax = v3 * e3.x; ay = v3 * e3.y; sx += ax; qx = fmaf(ax, ax, qx); sy += ay; qy = fmaf(ay, ay, qy);
    }
    for (; i < hi; i += GROUPS) {
        int   f = __ldcs(fids + i);
        float v = __ldcs(vals + i);
        float2 e = __ldg(emb2 + f * 32 + t);
        float ax = v * e.x, ay = v * e.y;
        sx += ax; qx = fmaf(ax, ax, qx);
        sy += ay; qy = fmaf(ay, ay, qy);
    }

    // combine 8 groups through shared memory
    __shared__ float ssx[GROUPS][32], ssy[GROUPS][32];
    __shared__ float sqx[GROUPS][32], sqy[GROUPS][32];
    ssx[g][t] = sx; ssy[g][t] = sy;
    sqx[g][t] = qx; sqy[g][t] = qy;
    __syncthreads();

    if (g == 0) {
        float Sx = sx, Sy = sy, Qx = qx, Qy = qy;
        #pragma unroll
        for (int k = 1; k < GROUPS; k++) {
            Sx += ssx[k][t]; Sy += ssy[k][t];
            Qx += sqx[k][t]; Qy += sqy[k][t];
        }
        float2 o;
        o.x = 0.5f * (Sx * Sx - Qx);
        o.y = 0.5f * (Sy * Sy - Qy);
        __stcs(((float2*)out) + b * 32 + t, o);   // output: single-use, evict-first
    }
}

extern "C" void kernel_launch(void* const* d_in, const int* in_sizes, int n_in,
                              void* d_out, int out_size)
{
    const float* emb  = (const float*)d_in[0];
    const float* vals = (const float*)d_in[1];
    const int*   bids = (const int*)d_in[2];
    const int*   fids = (const int*)d_in[3];
    float* out = (float*)d_out;

    int nnz   = in_sizes[1];
    int batch = out_size / EMBED;   // 4096

    int bblocks = (nnz + 1 + 255) / 256;
    boundary_kernel<<<bblocks, 256>>>(bids, nnz, batch);
    fm_main<<<batch, BLOCK>>>(emb, vals, fids, out);
}

// round 17
// speedup vs baseline: 1.0340x; 1.0340x over previous
#include <cuda_runtime.h>
#include <cuda_bf16.h>

// FM layer: out[b,:] = 0.5 * ((sum v*e)^2 - sum (v*e)^2), batch_ids sorted.
//
// FINAL — empirical argmax over 16 rounds (best total 41.28us; samples of
// this exact config: 41.28/41.47/41.47/41.70/41.73).
//
//   * boundary_kernel: sorted batch_ids -> CSR row starts, 1 elem/thread,
//     exactly-once transition writes, no atomics (~1.5us). Beat every
//     alternative: EPT 4/16/32, fused binary search (-4us), fused windowed
//     scan (-5us), fused flag hand-off (-2us), PDL (neutral).
//   * fm_main: 1 CTA per batch row, 8 groups x 32 threads (float2 lanes),
//     4-deep independent gather pipeline, 32 regs, 8 CTAs/SM (occ ~88%).
//     Pinned at the random-256B-row HBM ceiling (~4.35TB/s, ~165MB moved
//     vs ~154MB mandatory) across 7 structural + 3 cache-policy variants.
//
// Inputs:
//   d_in[0] feature_embedding float32 [1e6, 64]
//   d_in[1] feature_vals      float32 [819200]
//   d_in[2] batch_ids         int32   [819200] sorted
//   d_in[3] feat_ids          int32   [819200]
//   d_in[4] batch_size        int32   [1]
// Output float32 [4096, 64]

#define EMBED  64
#define GROUPS 8              // 8 warps per CTA, group-strided over the segment
#define BLOCK  256

__device__ int g_starts[4097];

// Sorted batch_ids -> CSR row starts. Exactly-once, no atomics.
__global__ void boundary_kernel(const int* __restrict__ bids, int nnz, int batch)
{
    int i = blockIdx.x * blockDim.x + threadIdx.x;
    if (i > nnz) return;
    int prev = (i == 0)   ? -1    : __ldg(bids + i - 1);
    int cur  = (i == nnz) ? batch : __ldg(bids + i);
    for (int b = prev + 1; b <= cur; b++)
        g_starts[b] = i;
}

__global__ __launch_bounds__(BLOCK, 8)
void fm_main(const float* __restrict__ emb,
             const float* __restrict__ vals,
             const int*   __restrict__ fids,
             float*       __restrict__ out)
{
    const int b = blockIdx.x;
    const int t = threadIdx.x & 31;     // float2 lane: dims [2t, 2t+1]
    const int g = threadIdx.x >> 5;     // warp/group 0..7

    const int lo = g_starts[b];
    const int hi = g_starts[b + 1];

    const float2* __restrict__ emb2 = (const float2*)emb;

    float sx = 0.f, sy = 0.f, qx = 0.f, qy = 0.f;

    int i = lo + g;
    // 4-deep independent gather pipeline per thread
    for (; i + 3 * GROUPS < hi; i += 4 * GROUPS) {
        int f0 = __ldg(fids + i);
        int f1 = __ldg(fids + i +     GROUPS);
        int f2 = __ldg(fids + i + 2 * GROUPS);
        int f3 = __ldg(fids + i + 3 * GROUPS);
        float v0 = __ldg(vals + i);
        float v1 = __ldg(vals + i +     GROUPS);
        float v2 = __ldg(vals + i + 2 * GROUPS);
        float v3 = __ldg(vals + i + 3 * GROUPS);
        float2 e0 = __ldg(emb2 + f0 * 32 + t);
        float2 e1 = __ldg(emb2 + f1 * 32 + t);
        float2 e2 = __ldg(emb2 + f2 * 32 + t);
        float2 e3 = __ldg(emb2 + f3 * 32 + t);

        float ax, ay;
        ax = v0 * e0.x; ay = v0 * e0.y; sx += ax; qx = fmaf(ax, ax, qx); sy += ay; qy = fmaf(ay, ay, qy);
        ax = v1 * e1.x; ay = v1 * e1.y; sx += ax; qx = fmaf(ax, ax, qx); sy += ay; qy = fmaf(ay, ay, qy);
        ax = v2 * e2.x; ay = v2 * e2.y; sx += ax; qx = fmaf(ax, ax, qx); sy += ay; qy = fmaf(ay, ay, qy);
        ax = v3 * e3.x; ay = v3 * e3.y; sx += ax; qx = fmaf(ax, ax, qx); sy += ay; qy = fmaf(ay, ay, qy);
    }
    for (; i < hi; i += GROUPS) {
        int   f = __ldg(fids + i);
        float v = __ldg(vals + i);
        float2 e = __ldg(emb2 + f * 32 + t);
        float ax = v * e.x, ay = v * e.y;
        sx += ax; qx = fmaf(ax, ax, qx);
        sy += ay; qy = fmaf(ay, ay, qy);
    }

    // combine 8 groups through shared memory
    __shared__ float ssx[GROUPS][32], ssy[GROUPS][32];
    __shared__ float sqx[GROUPS][32], sqy[GROUPS][32];
    ssx[g][t] = sx; ssy[g][t] = sy;
    sqx[g][t] = qx; sqy[g][t] = qy;
    __syncthreads();

    if (g == 0) {
        float Sx = sx, Sy = sy, Qx = qx, Qy = qy;
        #pragma unroll
        for (int k = 1; k < GROUPS; k++) {
            Sx += ssx[k][t]; Sy += ssy[k][t];
            Qx += sqx[k][t]; Qy += sqy[k][t];
        }
        float2 o;
        o.x = 0.5f * (Sx * Sx - Qx);
        o.y = 0.5f * (Sy * Sy - Qy);
        ((float2*)out)[b * 32 + t] = o;
    }
}

extern "C" void kernel_launch(void* const* d_in, const int* in_sizes, int n_in,
                              void* d_out, int out_size)
{
    const float* emb  = (const float*)d_in[0];
    const float* vals = (const float*)d_in[1];
    const int*   bids = (const int*)d_in[2];
    const int*   fids = (const int*)d_in[3];
    float* out = (float*)d_out;

    int nnz   = in_sizes[1];
    int batch = out_size / EMBED;   // 4096

    int bblocks = (nnz + 1 + 255) / 256;
    boundary_kernel<<<bblocks, 256>>>(bids, nnz, batch);
    fm_main<<<batch, BLOCK>>>(emb, vals, fids, out);
}